// round 1
// baseline (speedup 1.0000x reference)
#include <cuda_runtime.h>
#include <cuda_bf16.h>

#define NPTS  16384
#define NNBR  32
#define CIN   16
#define COUT  16
#define NB    16
#define GAMMA 10.0f
#define EPSF  1e-12f

// Scratch (allocation-free rule: __device__ globals)
__device__ float4 g_inputT[NPTS * 4];   // [n][q] : channels 4q..4q+3 of point n
__device__ float4 g_coords4[NPTS];      // padded coords

// ---------------------------------------------------------------------------
// Prep: transpose input (C,N)->(N,C) as float4 rows; pad coords to float4.
// ---------------------------------------------------------------------------
__global__ void prep_kernel(const float* __restrict__ input,
                            const float* __restrict__ coords) {
    int idx = blockIdx.x * blockDim.x + threadIdx.x;   // 0 .. NPTS*4-1
    if (idx >= NPTS * 4) return;
    int n = idx >> 2;
    int q = idx & 3;
    float4 v;
    v.x = input[(4 * q + 0) * NPTS + n];
    v.y = input[(4 * q + 1) * NPTS + n];
    v.z = input[(4 * q + 2) * NPTS + n];
    v.w = input[(4 * q + 3) * NPTS + n];
    g_inputT[idx] = v;
    if (q == 0) {
        float4 c;
        c.x = coords[n * 3 + 0];
        c.y = coords[n * 3 + 1];
        c.z = coords[n * 3 + 2];
        c.w = 0.0f;
        g_coords4[n] = c;
    }
}

// ---------------------------------------------------------------------------
// Main: 4 threads per point. Thread t owns bases 4t..4t+3, acc[4][16].
// Per neighbor: compute 4 rbf values (m-scaled), load own channel-quartet
// float4 (coalesced), SHFL-broadcast x across the 4-lane group, rank-1 update.
// Epilogue: contract with W (smem, warp-broadcast reads), butterfly-reduce
// across the 4-lane group, write output (O,N).
// ---------------------------------------------------------------------------
__global__ __launch_bounds__(256, 2)
void conv_kernel(const float* __restrict__ W,
                 const float* __restrict__ centers,
                 const float* __restrict__ mask,
                 const int*   __restrict__ neighbors,
                 float*       __restrict__ out) {
    __shared__ float4 Wsm[COUT * CIN * 4];   // [(o*16+i)*4 + t] = W[o][i][4t..4t+3]

    int tid = threadIdx.x;
    {
        const float4* W4 = (const float4*)W;
        #pragma unroll
        for (int j = 0; j < 4; j++)
            Wsm[tid + 256 * j] = W4[tid + 256 * j];
    }
    __syncthreads();

    const int t  = tid & 3;         // basis quartet owner
    const int pl = tid >> 2;        // point within block (0..63)
    const int n  = blockIdx.x * 64 + pl;

    const float4 pc = g_coords4[n];
    const float c0 = centers[4 * t + 0];
    const float c1 = centers[4 * t + 1];
    const float c2 = centers[4 * t + 2];
    const float c3 = centers[4 * t + 3];

    float acc0[16], acc1[16], acc2[16], acc3[16];
    #pragma unroll
    for (int i = 0; i < 16; i++) { acc0[i] = 0.f; acc1[i] = 0.f; acc2[i] = 0.f; acc3[i] = 0.f; }

    const int   base = n * NNBR;
    const float NGL2 = -GAMMA * 1.4426950408889634f;   // for exp via exp2

    #pragma unroll 4
    for (int k = 0; k < NNBR; k++) {
        const int   nbr = __ldg(&neighbors[base + k]);     // broadcast in 4-group
        const float m   = __ldg(&mask[base + k]);
        const float4 cc = g_coords4[nbr];                  // broadcast in 4-group
        const float dx = cc.x - pc.x;
        const float dy = cc.y - pc.y;
        const float dz = cc.z - pc.z;
        const float r  = sqrtf(fmaf(dx, dx, fmaf(dy, dy, fmaf(dz, dz, EPSF))));

        const float d0 = r - c0, d1 = r - c1, d2 = r - c2, d3 = r - c3;
        const float u0 = m * exp2f(NGL2 * d0 * d0);
        const float u1 = m * exp2f(NGL2 * d1 * d1);
        const float u2 = m * exp2f(NGL2 * d2 * d2);
        const float u3 = m * exp2f(NGL2 * d3 * d3);

        const float4 xq = g_inputT[nbr * 4 + t];           // own channel quartet

        #pragma unroll
        for (int q = 0; q < 4; q++) {
            const float x0 = __shfl_sync(0xFFFFFFFFu, xq.x, q, 4);
            const float x1 = __shfl_sync(0xFFFFFFFFu, xq.y, q, 4);
            const float x2 = __shfl_sync(0xFFFFFFFFu, xq.z, q, 4);
            const float x3 = __shfl_sync(0xFFFFFFFFu, xq.w, q, 4);
            const int i = 4 * q;
            acc0[i + 0] = fmaf(u0, x0, acc0[i + 0]);
            acc0[i + 1] = fmaf(u0, x1, acc0[i + 1]);
            acc0[i + 2] = fmaf(u0, x2, acc0[i + 2]);
            acc0[i + 3] = fmaf(u0, x3, acc0[i + 3]);
            acc1[i + 0] = fmaf(u1, x0, acc1[i + 0]);
            acc1[i + 1] = fmaf(u1, x1, acc1[i + 1]);
            acc1[i + 2] = fmaf(u1, x2, acc1[i + 2]);
            acc1[i + 3] = fmaf(u1, x3, acc1[i + 3]);
            acc2[i + 0] = fmaf(u2, x0, acc2[i + 0]);
            acc2[i + 1] = fmaf(u2, x1, acc2[i + 1]);
            acc2[i + 2] = fmaf(u2, x2, acc2[i + 2]);
            acc2[i + 3] = fmaf(u2, x3, acc2[i + 3]);
            acc3[i + 0] = fmaf(u3, x0, acc3[i + 0]);
            acc3[i + 1] = fmaf(u3, x1, acc3[i + 1]);
            acc3[i + 2] = fmaf(u3, x2, acc3[i + 2]);
            acc3[i + 3] = fmaf(u3, x3, acc3[i + 3]);
        }
    }

    // Epilogue: po[o] = sum_{i, own b} W[o][i][b] * acc[b][i]
    float po[COUT];
    #pragma unroll
    for (int o = 0; o < COUT; o++) po[o] = 0.f;

    #pragma unroll
    for (int o = 0; o < COUT; o++) {
        #pragma unroll
        for (int i = 0; i < CIN; i++) {
            const float4 w = Wsm[(o * CIN + i) * 4 + t];   // same addr across 8 pts -> broadcast
            po[o] = fmaf(w.x, acc0[i], po[o]);
            po[o] = fmaf(w.y, acc1[i], po[o]);
            po[o] = fmaf(w.z, acc2[i], po[o]);
            po[o] = fmaf(w.w, acc3[i], po[o]);
        }
    }

    // Butterfly all-reduce over the 4-lane group
    #pragma unroll
    for (int s = 1; s < 4; s <<= 1) {
        #pragma unroll
        for (int o = 0; o < COUT; o++)
            po[o] += __shfl_xor_sync(0xFFFFFFFFu, po[o], s, 4);
    }

    // Thread t writes outputs 4t..4t+3
    #pragma unroll
    for (int j = 0; j < 4; j++)
        out[(4 * t + j) * NPTS + n] = po[4 * t + j];
}

// ---------------------------------------------------------------------------
extern "C" void kernel_launch(void* const* d_in, const int* in_sizes, int n_in,
                              void* d_out, int out_size) {
    const float* input     = (const float*)d_in[0];   // (16, 16384)
    const float* coords    = (const float*)d_in[1];   // (16384, 3)
    const float* W         = (const float*)d_in[2];   // (16, 16, 16)
    const float* centers   = (const float*)d_in[3];   // (16,)
    const float* mask      = (const float*)d_in[4];   // (16384, 32)
    const int*   neighbors = (const int*)d_in[5];     // (16384, 32)
    float*       out       = (float*)d_out;           // (16, 16384)

    prep_kernel<<<(NPTS * 4 + 255) / 256, 256>>>(input, coords);
    conv_kernel<<<NPTS / 64, 256>>>(W, centers, mask, neighbors, out);
}